// round 15
// baseline (speedup 1.0000x reference)
#include <cuda_runtime.h>
#include <math.h>
#include <stdint.h>

#define BN   64
#define TN   512
#define BT   32768
#define DN   1536
#define C1   192
#define C4T  768
#define HN   256
#define G4   1024
#define LBL  20

// ---------------- scratch (static device memory) ------------------------------
__device__ uint32_t g_xnq [ (size_t)BT * DN / 4 ];
__device__ float    g_cv  [ (size_t)BT * C4T    ];
__device__ uint32_t g_coq [ (size_t)BT * C4T / 4];
__device__ float    g_gxf [ (size_t)BT * G4     ];
__device__ float    g_gxb [ (size_t)BT * G4     ];
__device__ float    g_h   [ (size_t)BT * 2 * HN ];
__device__ float    g_lg  [ (size_t)BT * LBL    ];
__device__ uint32_t g_wxqf[ (C4T / 4) * G4 ];
__device__ uint32_t g_wxqb[ (C4T / 4) * G4 ];
__device__ uint32_t g_cwq [ 10 * (DN / 4) * C1 ];

// ---------------- helpers -----------------------------------------------------
__device__ __forceinline__ uint32_t packbf(float lo, float hi) {
    uint32_t u;
    asm("cvt.rn.bf16x2.f32 %0, %1, %2;" : "=r"(u) : "f"(hi), "f"(lo));
    return u;
}
__device__ __forceinline__ uint32_t pack4e4m3(float e0, float e1, float e2, float e3) {
    uint16_t lo, hi;
    asm("cvt.rn.satfinite.e4m3x2.f32 %0, %1, %2;" : "=h"(lo) : "f"(e1), "f"(e0));
    asm("cvt.rn.satfinite.e4m3x2.f32 %0, %1, %2;" : "=h"(hi) : "f"(e3), "f"(e2));
    return (uint32_t)lo | ((uint32_t)hi << 16);
}
__device__ __forceinline__ uint32_t f2tf32(float f) {
    uint32_t u;
    asm("cvt.rna.tf32.f32 %0, %1;" : "=r"(u) : "f"(f));
    return u;
}
__device__ __forceinline__ float ftanh(float x) {
    float y;
    asm("tanh.approx.f32 %0, %1;" : "=f"(y) : "f"(x));
    return y;
}
__device__ __forceinline__ float fsig(float x) {
    return 0.5f * ftanh(0.5f * x) + 0.5f;
}
__device__ __forceinline__ void mma_fp8(float* c, uint32_t a0, uint32_t a1,
                                        uint32_t a2, uint32_t a3,
                                        uint32_t b0, uint32_t b1) {
    asm volatile(
        "mma.sync.aligned.m16n8k32.row.col.f32.e4m3.e4m3.f32 "
        "{%0,%1,%2,%3}, {%4,%5,%6,%7}, {%8,%9}, {%0,%1,%2,%3};\n"
        : "+f"(c[0]), "+f"(c[1]), "+f"(c[2]), "+f"(c[3])
        : "r"(a0), "r"(a1), "r"(a2), "r"(a3), "r"(b0), "r"(b1));
}
__device__ __forceinline__ void mma_bf16(float* c, uint32_t a0, uint32_t a1,
                                         uint32_t a2, uint32_t a3,
                                         uint32_t b0, uint32_t b1) {
    asm volatile(
        "mma.sync.aligned.m16n8k16.row.col.f32.bf16.bf16.f32 "
        "{%0,%1,%2,%3}, {%4,%5,%6,%7}, {%8,%9}, {%0,%1,%2,%3};\n"
        : "+f"(c[0]), "+f"(c[1]), "+f"(c[2]), "+f"(c[3])
        : "r"(a0), "r"(a1), "r"(a2), "r"(a3), "r"(b0), "r"(b1));
}
__device__ __forceinline__ void mma_tf32(float* c, uint32_t a0, uint32_t a1,
                                         uint32_t a2, uint32_t a3,
                                         uint32_t b0, uint32_t b1) {
    asm volatile(
        "mma.sync.aligned.m16n8k8.row.col.f32.tf32.tf32.f32 "
        "{%0,%1,%2,%3}, {%4,%5,%6,%7}, {%8,%9}, {%0,%1,%2,%3};\n"
        : "+f"(c[0]), "+f"(c[1]), "+f"(c[2]), "+f"(c[3])
        : "r"(a0), "r"(a1), "r"(a2), "r"(a3), "r"(b0), "r"(b1));
}
__device__ __forceinline__ void ldsm4(uint32_t* a, uint32_t saddr) {
    asm volatile("ldmatrix.sync.aligned.m8n8.x4.shared.b16 {%0,%1,%2,%3}, [%4];"
                 : "=r"(a[0]), "=r"(a[1]), "=r"(a[2]), "=r"(a[3]) : "r"(saddr));
}
__device__ __forceinline__ uint32_t smem_u32(const void* p) {
    uint32_t a;
    asm("{ .reg .u64 t; cvta.to.shared.u64 t, %1; cvt.u32.u64 %0, t; }"
        : "=r"(a) : "l"(p));
    return a;
}
#define MB_INIT(a, c) asm volatile("mbarrier.init.shared.b64 [%0], %1;" :: "r"(a), "r"((uint32_t)(c)) : "memory")
#define MB_WAIT(a, par) do { \
    asm volatile("{\n\t.reg .pred P1;\n\tWL%=:\n\t" \
        "mbarrier.try_wait.parity.acquire.cta.shared::cta.b64 P1, [%0], %1, 0x989680;\n\t" \
        "@P1 bra WD%=;\n\tbra WL%=;\n\tWD%=:\n\t}" :: "r"(a), "r"((uint32_t)(par)) : "memory"); } while (0)
#define MB_ARRIVE_REMOTE(a) \
    asm volatile("mbarrier.arrive.shared::cluster.b64 _, [%0];" :: "r"(a) : "memory")

#define AST2 20
#define BSTX 136
#define BST4 104
#define AST 36
#define BST 68

// ---------------- merged fp8 weight prepack -------------------------------------
__global__ __launch_bounds__(256) void pack_all_kernel(
    const float* __restrict__ wx_f, const float* __restrict__ wx_b,
    const float* __restrict__ w1, const float* __restrict__ w2,
    const float* __restrict__ w3, const float* __restrict__ w4,
    uint32_t* __restrict__ wxqf, uint32_t* __restrict__ wxqb,
    uint32_t* __restrict__ cwq)
{
    int idx = blockIdx.x * 256 + threadIdx.x;
    const int SX = (C4T / 4) * G4;
    if (idx < SX) {
        int kq = idx >> 10, n = idx & 1023;
        const float* s = wx_f + (size_t)(4 * kq) * G4 + n;
        wxqf[idx] = pack4e4m3(s[0], s[G4], s[2 * G4], s[3 * G4]);
        return;
    }
    idx -= SX;
    if (idx < SX) {
        int kq = idx >> 10, n = idx & 1023;
        const float* s = wx_b + (size_t)(4 * kq) * G4 + n;
        wxqb[idx] = pack4e4m3(s[0], s[G4], s[2 * G4], s[3 * G4]);
        return;
    }
    idx -= SX;
    const int T1 = (DN / 4) * C1;
    const float* src;
    uint32_t* dst;
    if (idx < 1 * T1)      { src = w1; dst = cwq; }
    else if (idx < 3 * T1) { src = w2; dst = cwq + (size_t)1 * T1; idx -= 1 * T1; }
    else if (idx < 6 * T1) { src = w3; dst = cwq + (size_t)3 * T1; idx -= 3 * T1; }
    else if (idx < 10 * T1){ src = w4; dst = cwq + (size_t)6 * T1; idx -= 6 * T1; }
    else return;
    int kqg = idx / C1, n = idx - kqg * C1;
    const float* s = src + (size_t)(4 * kqg) * C1 + n;
    dst[idx] = pack4e4m3(s[0], s[C1], s[2 * C1], s[3 * C1]);
}

// ---------------- LayerNorm 1: single-pass, register-cached ---------------------
__global__ __launch_bounds__(192) void ln1_kernel(
    const float* __restrict__ ha, const float* __restrict__ hb,
    const float* __restrict__ g,  const float* __restrict__ be,
    uint32_t* __restrict__ out4)
{
    int row = blockIdx.x;
    int tid = threadIdx.x;
    int d0 = tid * 8;
    float4 v0, v1;
    if (tid < 96) {
        const float* A = ha + (size_t)row * 768 + d0;
        v0 = *reinterpret_cast<const float4*>(A);
        v1 = *reinterpret_cast<const float4*>(A + 4);
    } else {
        const float* B = hb + (size_t)row * 768 + (d0 - 768);
        v0 = *reinterpret_cast<const float4*>(B);
        v1 = *reinterpret_cast<const float4*>(B + 4);
    }
    float s  = v0.x + v0.y + v0.z + v0.w + v1.x + v1.y + v1.z + v1.w;
    float s2 = v0.x*v0.x + v0.y*v0.y + v0.z*v0.z + v0.w*v0.w
             + v1.x*v1.x + v1.y*v1.y + v1.z*v1.z + v1.w*v1.w;
#pragma unroll
    for (int o = 16; o; o >>= 1) {
        s  += __shfl_xor_sync(0xffffffffu, s, o);
        s2 += __shfl_xor_sync(0xffffffffu, s2, o);
    }
    __shared__ float ws[6], wq[6];
    int wid = tid >> 5;
    if ((tid & 31) == 0) { ws[wid] = s; wq[wid] = s2; }
    __syncthreads();
    float S = ws[0] + ws[1] + ws[2] + ws[3] + ws[4] + ws[5];
    float Q = wq[0] + wq[1] + wq[2] + wq[3] + wq[4] + wq[5];
    float mean = S * (1.f / DN);
    float var  = Q * (1.f / DN) - mean * mean;
    float rstd = rsqrtf(var + 1e-5f);
    float4 g0 = *reinterpret_cast<const float4*>(g + d0);
    float4 g1 = *reinterpret_cast<const float4*>(g + d0 + 4);
    float4 b0 = *reinterpret_cast<const float4*>(be + d0);
    float4 b1 = *reinterpret_cast<const float4*>(be + d0 + 4);
    uint32_t* O = out4 + (size_t)row * (DN / 4) + tid * 2;
    O[0] = pack4e4m3((v0.x - mean) * rstd * g0.x + b0.x,
                     (v0.y - mean) * rstd * g0.y + b0.y,
                     (v0.z - mean) * rstd * g0.z + b0.z,
                     (v0.w - mean) * rstd * g0.w + b0.w);
    O[1] = pack4e4m3((v1.x - mean) * rstd * g1.x + b1.x,
                     (v1.y - mean) * rstd * g1.y + b1.y,
                     (v1.z - mean) * rstd * g1.z + b1.z,
                     (v1.w - mean) * rstd * g1.w + b1.w);
}

// ---------------- LayerNorm 2: single-pass, register-cached ---------------------
__global__ __launch_bounds__(192) void ln2_kernel(
    const float* __restrict__ in, const float* __restrict__ g,
    const float* __restrict__ be, uint32_t* __restrict__ out4)
{
    int row = blockIdx.x;
    int tid = threadIdx.x;
    int d0 = tid * 4;
    float4 v = *reinterpret_cast<const float4*>(in + (size_t)row * C4T + d0);
    float s  = v.x + v.y + v.z + v.w;
    float s2 = v.x*v.x + v.y*v.y + v.z*v.z + v.w*v.w;
#pragma unroll
    for (int o = 16; o; o >>= 1) {
        s  += __shfl_xor_sync(0xffffffffu, s, o);
        s2 += __shfl_xor_sync(0xffffffffu, s2, o);
    }
    __shared__ float ws[6], wq[6];
    int wid = tid >> 5;
    if ((tid & 31) == 0) { ws[wid] = s; wq[wid] = s2; }
    __syncthreads();
    float S = ws[0] + ws[1] + ws[2] + ws[3] + ws[4] + ws[5];
    float Q = wq[0] + wq[1] + wq[2] + wq[3] + wq[4] + wq[5];
    float mean = S * (1.f / C4T);
    float var  = Q * (1.f / C4T) - mean * mean;
    float rstd = rsqrtf(var + 1e-5f);
    float4 gg = *reinterpret_cast<const float4*>(g + d0);
    float4 bb = *reinterpret_cast<const float4*>(be + d0);
    out4[(size_t)row * (C4T / 4) + tid] =
        pack4e4m3((v.x - mean) * rstd * gg.x + bb.x,
                  (v.y - mean) * rstd * gg.y + bb.y,
                  (v.z - mean) * rstd * gg.z + bb.z,
                  (v.w - mean) * rstd * gg.w + bb.w);
}

// ---------------- fp8 dual xWx GEMM (unchanged) ---------------------------------
__global__ __launch_bounds__(256) void gemm_fp8_dual_kernel(
    const uint32_t* __restrict__ A4,
    const uint32_t* __restrict__ Wqf, const uint32_t* __restrict__ Wqb,
    const float* __restrict__ biasf, const float* __restrict__ biasb,
    float* __restrict__ Cf, float* __restrict__ Cb)
{
    const int Nn = G4;
    __shared__ uint32_t As[2][128 * AST2];
    __shared__ uint32_t Bs[2][16 * BSTX];
    int tid = threadIdx.x;
    int half = blockIdx.y >> 3;
    int n0 = (blockIdx.y & 7) * 128;
    const uint32_t* Wq   = half ? Wqb : Wqf;
    const float*    bias = half ? biasb : biasf;
    float*          Cc   = half ? Cb : Cf;
    int m0 = blockIdx.x * 128;
    int wid = tid >> 5, lane = tid & 31;
    int wm0 = (wid & 3) * 32, wn0 = (wid >> 2) * 64;
    int g = lane >> 2, tg = lane & 3;
    const int K4 = C4T >> 2;

    float acc[2][8][4];
#pragma unroll
    for (int mt = 0; mt < 2; mt++)
#pragma unroll
        for (int nt = 0; nt < 8; nt++)
#pragma unroll
            for (int i = 0; i < 4; i++) acc[mt][nt][i] = 0.f;

    uint32_t abase[2];
#pragma unroll
    for (int sb = 0; sb < 2; sb++)
        abase[sb] = (uint32_t)__cvta_generic_to_shared(
            &As[sb][(wm0 + (lane & 15)) * AST2 + (lane >> 4) * 4]);

    uint4 pa[2], pb[2];
    const int nk = C4T / 64;
    auto loadA = [&](int kt) {
#pragma unroll
        for (int j = 0; j < 2; j++) {
            int idx4 = tid + j * 256;
            int row = idx4 >> 2, qc = (idx4 & 3) << 2;
            pa[j] = *reinterpret_cast<const uint4*>(A4 + (size_t)(m0 + row) * K4 + kt * 16 + qc);
        }
    };
    auto loadB = [&](int kt) {
#pragma unroll
        for (int j = 0; j < 2; j++) {
            int idx4 = tid + j * 256;
            int kp = idx4 >> 5, nc = (idx4 & 31) << 2;
            pb[j] = *reinterpret_cast<const uint4*>(Wq + (size_t)(kt * 16 + kp) * Nn + n0 + nc);
        }
    };
    auto stage = [&](int sb) {
#pragma unroll
        for (int j = 0; j < 2; j++) {
            int idx4 = tid + j * 256;
            int row = idx4 >> 2, qc = (idx4 & 3) << 2;
            *reinterpret_cast<uint4*>(&As[sb][row * AST2 + qc]) = pa[j];
        }
#pragma unroll
        for (int j = 0; j < 2; j++) {
            int idx4 = tid + j * 256;
            int kp = idx4 >> 5, nc = (idx4 & 31) << 2;
            *reinterpret_cast<uint4*>(&Bs[sb][kp * BSTX + nc]) = pb[j];
        }
    };

    loadA(0); loadB(0);
    stage(0);
    __syncthreads();
    for (int kt = 0; kt < nk; kt++) {
        int cur = kt & 1;
        if (kt + 1 < nk) { loadA(kt + 1); loadB(kt + 1); }
        const uint32_t* Bc = Bs[cur];
        uint32_t ab = abase[cur];
#pragma unroll
        for (int ks = 0; ks < 2; ks++) {
            int kk4 = ks * 8;
            uint32_t a[2][4], b[8][2];
#pragma unroll
            for (int mt = 0; mt < 2; mt++)
                ldsm4(a[mt], ab + (uint32_t)((mt * 16 * AST2 + kk4) * 4));
#pragma unroll
            for (int nt = 0; nt < 8; nt++) {
                int col = wn0 + nt * 8 + g;
                b[nt][0] = Bc[(kk4 + tg    ) * BSTX + col];
                b[nt][1] = Bc[(kk4 + tg + 4) * BSTX + col];
            }
#pragma unroll
            for (int mt = 0; mt < 2; mt++)
#pragma unroll
                for (int nt = 0; nt < 8; nt++)
                    mma_fp8(acc[mt][nt], a[mt][0], a[mt][1], a[mt][2], a[mt][3],
                            b[nt][0], b[nt][1]);
        }
        if (kt + 1 < nk) {
            stage(cur ^ 1);
            __syncthreads();
        }
    }
#pragma unroll
    for (int mt = 0; mt < 2; mt++)
#pragma unroll
        for (int nt = 0; nt < 8; nt++) {
            int col = n0 + wn0 + nt * 8 + 2 * tg;
#pragma unroll
            for (int i = 0; i < 4; i++) {
                int row = m0 + wm0 + mt * 16 + g + (i >> 1) * 8;
                int c = col + (i & 1);
                Cc[(size_t)row * Nn + c] = acc[mt][nt][i] + bias[c];
            }
        }
}

// ---------------- Conv fp8: 128x96 tile, heavy-first, 2x parallelism ------------
// grid (BT/128, 8): conv = 3 - (y>>1) (heavy blocks first), nloc0 = (y&1)*96.
__global__ __launch_bounds__(256) void conv_fp8_kernel(
    const uint32_t* __restrict__ xnq, const uint32_t* __restrict__ cwq,
    const float* __restrict__ cb1, const float* __restrict__ cb2,
    const float* __restrict__ cb3, const float* __restrict__ cb4,
    float* __restrict__ cv)
{
    __shared__ uint32_t As[2][128 * AST2];
    __shared__ uint32_t Bs[2][16 * BST4];
    int tid = threadIdx.x;
    int m0 = blockIdx.x * 128;
    int conv = 3 - (blockIdx.y >> 1);
    int nloc0 = (blockIdx.y & 1) * 96;
    int bidx = m0 >> 9;
    int t0   = m0 & 511;
    int tap0 = (conv == 0) ? 0 : (conv == 1) ? 1 : (conv == 2) ? 3 : 6;
    const float* bias = (conv == 0) ? cb1 : (conv == 1) ? cb2 : (conv == 2) ? cb3 : cb4;
    int ntaps = conv + 1;
    int dmin  = (conv < 2) ? 1 : 0;

    int wid = tid >> 5, lane = tid & 31;
    int wm0 = (wid & 3) * 32, wn0 = (wid >> 2) * 48;
    int g = lane >> 2, tg = lane & 3;

    float acc[2][6][4];
#pragma unroll
    for (int mt = 0; mt < 2; mt++)
#pragma unroll
        for (int nt = 0; nt < 6; nt++)
#pragma unroll
            for (int i = 0; i < 4; i++) acc[mt][nt][i] = 0.f;

    uint32_t abase[2];
#pragma unroll
    for (int sb = 0; sb < 2; sb++)
        abase[sb] = (uint32_t)__cvta_generic_to_shared(
            &As[sb][(wm0 + (lane & 15)) * AST2 + (lane >> 4) * 4]);

    const int nkt = DN / 64;           // 24 per tap
    int total = ntaps * nkt;
    const int K4 = DN / 4;

    uint4 pa[2], pb[2];
    auto loadA = [&](int it) {
        int ti = it / nkt, kt = it - ti * nkt;
        int shift = dmin + ti - 1;
#pragma unroll
        for (int j = 0; j < 2; j++) {
            int idx4 = tid + j * 256;
            int row = idx4 >> 2, qc = (idx4 & 3) << 2;
            int tsrc = t0 + row + shift;
            if (tsrc >= 0 && tsrc < TN)
                pa[j] = *reinterpret_cast<const uint4*>(
                    xnq + (size_t)((bidx << 9) + tsrc) * K4 + kt * 16 + qc);
            else
                pa[j] = make_uint4(0u, 0u, 0u, 0u);
        }
    };
    // B tile: 16 kp x 96 cols = 384 uint4
    auto loadB = [&](int it) {
        int ti = it / nkt, kt = it - ti * nkt;
#pragma unroll
        for (int j = 0; j < 2; j++) {
            int idx4 = tid + j * 256;
            if (idx4 < 384) {
                int kp = idx4 / 24, nc = (idx4 % 24) << 2;
                pb[j] = *reinterpret_cast<const uint4*>(
                    cwq + ((size_t)(tap0 + ti) * (DN / 4) + kt * 16 + kp) * C1 + nloc0 + nc);
            }
        }
    };
    auto stage = [&](int sb) {
#pragma unroll
        for (int j = 0; j < 2; j++) {
            int idx4 = tid + j * 256;
            int row = idx4 >> 2, qc = (idx4 & 3) << 2;
            *reinterpret_cast<uint4*>(&As[sb][row * AST2 + qc]) = pa[j];
        }
#pragma unroll
        for (int j = 0; j < 2; j++) {
            int idx4 = tid + j * 256;
            if (idx4 < 384) {
                int kp = idx4 / 24, nc = (idx4 % 24) << 2;
                *reinterpret_cast<uint4*>(&Bs[sb][kp * BST4 + nc]) = pb[j];
            }
        }
    };

    loadA(0); loadB(0);
    stage(0);
    __syncthreads();
    for (int it = 0; it < total; it++) {
        int cur = it & 1;
        if (it + 1 < total) { loadA(it + 1); loadB(it + 1); }
        const uint32_t* Bc = Bs[cur];
        uint32_t ab = abase[cur];
#pragma unroll
        for (int ks = 0; ks < 2; ks++) {
            int kk4 = ks * 8;
            uint32_t a[2][4], b[6][2];
#pragma unroll
            for (int mt = 0; mt < 2; mt++)
                ldsm4(a[mt], ab + (uint32_t)((mt * 16 * AST2 + kk4) * 4));
#pragma unroll
            for (int nt = 0; nt < 6; nt++) {
                int col = wn0 + nt * 8 + g;
                b[nt][0] = Bc[(kk4 + tg    ) * BST4 + col];
                b[nt][1] = Bc[(kk4 + tg + 4) * BST4 + col];
            }
#pragma unroll
            for (int mt = 0; mt < 2; mt++)
#pragma unroll
                for (int nt = 0; nt < 6; nt++)
                    mma_fp8(acc[mt][nt], a[mt][0], a[mt][1], a[mt][2], a[mt][3],
                            b[nt][0], b[nt][1]);
        }
        if (it + 1 < total) {
            stage(cur ^ 1);
            __syncthreads();
        }
    }
#pragma unroll
    for (int mt = 0; mt < 2; mt++)
#pragma unroll
        for (int nt = 0; nt < 6; nt++) {
            int cl = wn0 + nt * 8 + 2 * tg;
#pragma unroll
            for (int i = 0; i < 4; i++) {
                int row = m0 + wm0 + mt * 16 + g + (i >> 1) * 8;
                int c   = cl + (i & 1);
                float v = acc[mt][nt][i] + bias[nloc0 + c];
                cv[(size_t)row * C4T + conv * C1 + nloc0 + c] = fmaxf(v, 0.f);
            }
        }
}

// ---------------- TF32 GEMM (logits) --------------------------------------------
__global__ __launch_bounds__(256) void gemm_tf32_kernel(
    const float* __restrict__ A, const float* __restrict__ W,
    const float* __restrict__ bias, float* __restrict__ Cc,
    int M, int Nn, int Kk)
{
    __shared__ uint32_t As[128 * AST];
    __shared__ uint32_t Bs[32 * BST];
    int tid = threadIdx.x;
    int m0 = blockIdx.x * 128, n0 = blockIdx.y * 64;
    int wid = tid >> 5, lane = tid & 31;
    int wm0 = (wid & 3) * 32, wn0 = (wid >> 2) * 32;
    int g = lane >> 2, tg = lane & 3;
    float acc[2][4][4];
#pragma unroll
    for (int mt = 0; mt < 2; mt++)
#pragma unroll
        for (int nt = 0; nt < 4; nt++)
#pragma unroll
            for (int i = 0; i < 4; i++) acc[mt][nt][i] = 0.f;
    float4 pa[4], pb[2];
    int nk = Kk / 32;
    auto loadA = [&](int kt) {
#pragma unroll
        for (int j = 0; j < 4; j++) {
            int idx4 = tid + j * 256;
            int row = idx4 >> 3, kc = (idx4 & 7) << 2;
            pa[j] = *reinterpret_cast<const float4*>(A + (size_t)(m0 + row) * Kk + kt * 32 + kc);
        }
    };
    auto loadB = [&](int kt) {
#pragma unroll
        for (int j = 0; j < 2; j++) {
            int idx4 = tid + j * 256;
            int row = idx4 >> 4, nc = (idx4 & 15) << 2;
            int ncol = n0 + nc;
            const float* Wr = W + (size_t)(kt * 32 + row) * Nn;
            float4 v;
            if (ncol + 3 < Nn) v = *reinterpret_cast<const float4*>(Wr + ncol);
            else {
                v.x = (ncol + 0 < Nn) ? Wr[ncol + 0] : 0.f;
                v.y = (ncol + 1 < Nn) ? Wr[ncol + 1] : 0.f;
                v.z = (ncol + 2 < Nn) ? Wr[ncol + 2] : 0.f;
                v.w = (ncol + 3 < Nn) ? Wr[ncol + 3] : 0.f;
            }
            pb[j] = v;
        }
    };
    auto stage = [&]() {
#pragma unroll
        for (int j = 0; j < 4; j++) {
            int idx4 = tid + j * 256;
            int row = idx4 >> 3, kc = (idx4 & 7) << 2;
            As[row * AST + kc + 0] = f2tf32(pa[j].x);
            As[row * AST + kc + 1] = f2tf32(pa[j].y);
            As[row * AST + kc + 2] = f2tf32(pa[j].z);
            As[row * AST + kc + 3] = f2tf32(pa[j].w);
        }
#pragma unroll
        for (int j = 0; j < 2; j++) {
            int idx4 = tid + j * 256;
            int row = idx4 >> 4, nc = (idx4 & 15) << 2;
            Bs[row * BST + nc + 0] = f2tf32(pb[j].x);
            Bs[row * BST + nc + 1] = f2tf32(pb[j].y);
            Bs[row * BST + nc + 2] = f2tf32(pb[j].z);
            Bs[row * BST + nc + 3] = f2tf32(pb[j].w);
        }
    };
    loadA(0); loadB(0);
    for (int kt = 0; kt < nk; kt++) {
        __syncthreads();
        stage();
        __syncthreads();
        if (kt + 1 < nk) { loadA(kt + 1); loadB(kt + 1); }
#pragma unroll
        for (int ks = 0; ks < 4; ks++) {
            int kk = ks * 8;
            uint32_t a[2][4], b[4][2];
#pragma unroll
            for (int mt = 0; mt < 2; mt++) {
                int r0 = wm0 + mt * 16 + g;
                a[mt][0] = As[(r0    ) * AST + kk + tg];
                a[mt][1] = As[(r0 + 8) * AST + kk + tg];
                a[mt][2] = As[(r0    ) * AST + kk + tg + 4];
                a[mt][3] = As[(r0 + 8) * AST + kk + tg + 4];
            }
#pragma unroll
            for (int nt = 0; nt < 4; nt++) {
                int col = wn0 + nt * 8 + g;
                b[nt][0] = Bs[(kk + tg    ) * BST + col];
                b[nt][1] = Bs[(kk + tg + 4) * BST + col];
            }
#pragma unroll
            for (int mt = 0; mt < 2; mt++)
#pragma unroll
                for (int nt = 0; nt < 4; nt++)
                    mma_tf32(acc[mt][nt], a[mt][0], a[mt][1], a[mt][2], a[mt][3],
                             b[nt][0], b[nt][1]);
        }
    }
#pragma unroll
    for (int mt = 0; mt < 2; mt++)
#pragma unroll
        for (int nt = 0; nt < 4; nt++) {
            int col = n0 + wn0 + nt * 8 + 2 * tg;
#pragma unroll
            for (int i = 0; i < 4; i++) {
                int row = m0 + wm0 + mt * 16 + g + (i >> 1) * 8;
                int c = col + (i & 1);
                if (c < Nn) Cc[(size_t)row * Nn + c] = acc[mt][nt][i] + bias[c];
            }
        }
}

// ---------------- LSTM: 4-CTA cluster, mbarrier handoff (unchanged R13) ---------
#define LSW   (256 * 132 * 4)
#define LSH2  (2 * 128 * 8 * 4)
#define LSZ   (256 * 5 * 4)
#define LSMB  (LSW + LSH2 + LSZ)
#define LS_TOTAL (LSMB + 16)

__global__ void __cluster_dims__(4, 1, 1) __launch_bounds__(256)
lstm_cluster_kernel(
    const float* __restrict__ gxf, const float* __restrict__ gxb,
    const float* __restrict__ wh_f, const float* __restrict__ wh_b,
    const int* __restrict__ amask, float* __restrict__ hout)
{
    extern __shared__ char sm_[];
    uint32_t* whs2 = (uint32_t*)sm_;
    uint32_t* h2   = (uint32_t*)(sm_ + LSW);
    float*    zbuf = (float*)(sm_ + LSW + LSH2);
    uint32_t  mb   = smem_u32(sm_ + LSMB);

    int tid = threadIdx.x;
    uint32_t rank;
    asm("mov.u32 %0, %%cluster_ctarank;" : "=r"(rank));
    int grp = blockIdx.x >> 2;
    int dir = grp >> 4;
    int b0  = (grp & 15) * 4;
    const float* __restrict__ Wh = dir ? wh_b : wh_f;
    const float* __restrict__ gx = dir ? gxb : gxf;

    for (int i = tid; i < 256 * 128; i += 256) {
        int lcol = i >> 7, kp = i & 127;
        int gcol = ((lcol >> 6) << 8) + (int)rank * 64 + (lcol & 63);
        whs2[lcol * 132 + kp] = packbf(Wh[(2 * kp) * G4 + gcol],
                                       Wh[(2 * kp + 1) * G4 + gcol]);
    }
    for (int i = tid; i < 2048; i += 256) h2[i] = 0u;
    if (tid == 0) { MB_INIT(mb, 4); MB_INIT(mb + 8, 4); }

    int lane = tid & 31, wrp = tid >> 5;
    int g = lane >> 2, tg = lane & 3;
    int pb = tid >> 6, pj = tid & 63;
    int bb = b0 + pb;
    float h_r = 0.f, c_r = 0.f, op_r = 0.f;

    uint32_t ha[2][4];
    {
        int k = (int)rank * 64 + pj;
        uint32_t loc;
        const void* p = (const void*)((const char*)h2 + ((k >> 1) * 8 + pb) * 4 + (k & 1) * 2);
        asm("{ .reg .u64 t; cvta.to.shared.u64 t, %1; cvt.u32.u64 %0, t; }"
            : "=r"(loc) : "l"(p));
#pragma unroll
        for (int bf = 0; bf < 2; bf++) {
            uint32_t off = loc + bf * 4096;
#pragma unroll
            for (int r = 0; r < 4; r++)
                asm("mapa.shared::cluster.u32 %0, %1, %2;"
                    : "=r"(ha[bf][r]) : "r"(off), "r"(r));
        }
    }
    uint32_t mba[2][4];
#pragma unroll
    for (int bf = 0; bf < 2; bf++)
#pragma unroll
        for (int r = 0; r < 4; r++)
            asm("mapa.shared::cluster.u32 %0, %1, %2;"
                : "=r"(mba[bf][r]) : "r"(mb + bf * 8), "r"(r));

    asm volatile("barrier.cluster.arrive.aligned;" ::: "memory");
    asm volatile("barrier.cluster.wait.aligned;"   ::: "memory");

    int buf = 0, ph0 = 0, ph1 = 0;
    for (int s = 0; s < TN; s++) {
        int t = dir ? (TN - 1 - s) : s;
        size_t gb = ((size_t)(bb * TN + t)) * G4 + (size_t)rank * 64 + pj;
        float gx0 = gx[gb], gx1 = gx[gb + 256], gx2 = gx[gb + 512], gx3 = gx[gb + 768];
        int mv = amask[bb * TN + t];

        if (s > 0) {
            if (buf == 0) { MB_WAIT(mb, ph0);     ph0 ^= 1; }
            else          { MB_WAIT(mb + 8, ph1); ph1 ^= 1; }
        }

        const uint32_t* h2c = h2 + buf * 1024;
        float d0[4] = {0,0,0,0}, d1[4] = {0,0,0,0};
        float e0[4] = {0,0,0,0}, e1[4] = {0,0,0,0};
        int r0 = wrp * 32 + g;
#pragma unroll
        for (int kt = 0; kt < 8; kt++) {
            int kA = kt * 8, kB = (kt + 8) * 8;
            uint32_t bqA0 = h2c[(kA + tg) * 8 + g];
            uint32_t bqA1 = h2c[(kA + tg + 4) * 8 + g];
            uint32_t bqB0 = h2c[(kB + tg) * 8 + g];
            uint32_t bqB1 = h2c[(kB + tg + 4) * 8 + g];
            uint32_t a0, a1, a2, a3;
            a0 = whs2[(r0     ) * 132 + kA + tg];
            a1 = whs2[(r0 +  8) * 132 + kA + tg];
            a2 = whs2[(r0     ) * 132 + kA + tg + 4];
            a3 = whs2[(r0 +  8) * 132 + kA + tg + 4];
            mma_bf16(d0, a0, a1, a2, a3, bqA0, bqA1);
            a0 = whs2[(r0 + 16) * 132 + kA + tg];
            a1 = whs2[(r0 + 24) * 132 + kA + tg];
            a2 = whs2[(r0 + 16) * 132 + kA + tg + 4];
            a3 = whs2[(r0 + 24) * 132 + kA + tg + 4];
            mma_bf16(d1, a0, a1, a2, a3, bqA0, bqA1);
            a0 = whs2[(r0     ) * 132 + kB + tg];
            a1 = whs2[(r0 +  8) * 132 + kB + tg];
            a2 = whs2[(r0     ) * 132 + kB + tg + 4];
            a3 = whs2[(r0 +  8) * 132 + kB + tg + 4];
            mma_bf16(e0, a0, a1, a2, a3, bqB0, bqB1);
            a0 = whs2[(r0 + 16) * 132 + kB + tg];
            a1 = whs2[(r0 + 24) * 132 + kB + tg];
            a2 = whs2[(r0 + 16) * 132 + kB + tg + 4];
            a3 = whs2[(r0 + 24) * 132 + kB + tg + 4];
            mma_bf16(e1, a0, a1, a2, a3, bqB0, bqB1);
        }
        if (tg < 2) {
#pragma unroll
            for (int i = 0; i < 4; i++) {
                int col = 2 * tg + (i & 1);
                zbuf[(r0 + (i >> 1) * 8     ) * 5 + col] = d0[i] + e0[i];
                zbuf[(r0 + (i >> 1) * 8 + 16) * 5 + col] = d1[i] + e1[i];
            }
        }
        __syncthreads();

        int nb = buf ^ 1;
        {
            float zi = zbuf[(      pj) * 5 + pb] + gx0;
            float zf = zbuf[( 64 + pj) * 5 + pb] + gx1;
            float zg = zbuf[(128 + pj) * 5 + pb] + gx2;
            float zo = zbuf[(192 + pj) * 5 + pb] + gx3;
            float ii = fsig(zi);
            float ff = fsig(zf);
            float gg = ftanh(zg);
            float oo = fsig(zo);
            float cn = ff * c_r + ii * gg;
            float hn = oo * ftanh(cn);
            bool m = mv != 0;
            float hq = m ? hn : h_r;
            c_r  = m ? cn : c_r;
            op_r = m ? hn : op_r;
            h_r  = hq;
            hout[((size_t)(bb * TN + t)) * (2 * HN) + dir * HN + (int)rank * 64 + pj] = op_r;
            uint16_t hb16;
            asm("cvt.rn.bf16.f32 %0, %1;" : "=h"(hb16) : "f"(hq));
#pragma unroll
            for (int r = 0; r < 4; r++)
                asm volatile("st.shared::cluster.b16 [%0], %1;"
                             :: "r"(ha[nb][r]), "h"(hb16) : "memory");
        }
        __syncthreads();
        if (tid == 0) {
            asm volatile("fence.acq_rel.cluster;" ::: "memory");
#pragma unroll
            for (int r = 0; r < 4; r++)
                MB_ARRIVE_REMOTE(mba[nb][r]);
        }
        buf = nb;
    }
    asm volatile("barrier.cluster.arrive.aligned;" ::: "memory");
    asm volatile("barrier.cluster.wait.aligned;"   ::: "memory");
}

// ---------------- CRF: prefetched emits + fast math ------------------------------
__global__ __launch_bounds__(32) void crf_kernel(
    const int* __restrict__ inputs, const int* __restrict__ targets,
    const float* __restrict__ trans, const float* __restrict__ logits,
    float* __restrict__ out)
{
    int b = blockIdx.x;
    int lane = threadIdx.x;
    __shared__ float tr[LBL * LBL];
    __shared__ float alpha[LBL];
    for (int i = lane; i < LBL * LBL; i += 32) tr[i] = trans[i];
    int cnt = 0;
    for (int t = lane; t < TN; t += 32) cnt += (inputs[b * TN + t] != 0);
#pragma unroll
    for (int o = 16; o; o >>= 1) cnt += __shfl_xor_sync(0xffffffffu, cnt, o);
    int seqlen = cnt;
    const float* lg = logits + (size_t)b * TN * LBL;
    const int*   tg = targets + b * TN;
    float us = 0.f, bs = 0.f;
    for (int t = lane; t < TN; t += 32) {
        if (t < seqlen) us += lg[t * LBL + tg[t]];
        if (t >= 1 && t < seqlen) bs += tr[tg[t - 1] * LBL + tg[t]];
    }
#pragma unroll
    for (int o = 16; o; o >>= 1) {
        us += __shfl_xor_sync(0xffffffffu, us, o);
        bs += __shfl_xor_sync(0xffffffffu, bs, o);
    }
    __syncwarp();
    if (lane < LBL) alpha[lane] = lg[lane];
    __syncwarp();

    float emit = (lane < LBL) ? lg[LBL + lane] : 0.f;
    for (int t = 1; t < TN; t++) {
        float emitN = (lane < LBL && t + 1 < TN) ? lg[(t + 1) * LBL + lane] : 0.f;
        float newv = 0.f;
        if (lane < LBL) {
            float m = -1e30f;
#pragma unroll
            for (int i = 0; i < LBL; i++) m = fmaxf(m, alpha[i] + tr[i * LBL + lane]);
            float ss = 0.f;
#pragma unroll
            for (int i = 0; i < LBL; i++) ss += __expf(alpha[i] + tr[i * LBL + lane] - m);
            newv = m + __logf(ss) + emit;
        }
        __syncwarp();
        if (lane < LBL && t < seqlen) alpha[lane] = newv;
        __syncwarp();
        emit = emitN;
    }
    float a = (lane < LBL) ? alpha[lane] : -1e30f;
    float mx = a;
#pragma unroll
    for (int o = 16; o; o >>= 1) mx = fmaxf(mx, __shfl_xor_sync(0xffffffffu, mx, o));
    float e = (lane < LBL) ? __expf(a - mx) : 0.f;
#pragma unroll
    for (int o = 16; o; o >>= 1) e += __shfl_xor_sync(0xffffffffu, e, o);
    float lognorm = mx + __logf(e);
    if (lane == 0) out[b] = us + bs - lognorm;
}

// ---------------- launch -----------------------------------------------------------
extern "C" void kernel_launch(void* const* d_in, const int* in_sizes, int n_in,
                              void* d_out, int out_size)
{
    const int*   inputs = (const int*)  d_in[0];
    const int*   amask  = (const int*)  d_in[1];
    const int*   targets= (const int*)  d_in[2];
    const float* hid_a  = (const float*)d_in[3];
    const float* hid_b  = (const float*)d_in[4];
    const float* ln1_g  = (const float*)d_in[5];
    const float* ln1_b  = (const float*)d_in[6];
    const float* w1 = (const float*)d_in[7];
    const float* b1 = (const float*)d_in[8];
    const float* w2 = (const float*)d_in[9];
    const float* b2 = (const float*)d_in[10];
    const float* w3 = (const float*)d_in[11];
    const float* b3 = (const float*)d_in[12];
    const float* w4 = (const float*)d_in[13];
    const float* b4 = (const float*)d_in[14];
    const float* ln2_g = (const float*)d_in[15];
    const float* ln2_b = (const float*)d_in[16];
    const float* wx_f  = (const float*)d_in[17];
    const float* wh_f  = (const float*)d_in[18];
    const float* bf    = (const float*)d_in[19];
    const float* wx_b  = (const float*)d_in[20];
    const float* wh_b  = (const float*)d_in[21];
    const float* bb    = (const float*)d_in[22];
    const float* wd    = (const float*)d_in[23];
    const float* bd    = (const float*)d_in[24];
    const float* trans = (const float*)d_in[25];

    uint32_t *xnq, *coq, *wxqf, *wxqb, *cwq;
    float *cv, *gxf, *gxb, *hh, *lg;
    cudaGetSymbolAddress((void**)&xnq,  g_xnq);
    cudaGetSymbolAddress((void**)&cv,   g_cv);
    cudaGetSymbolAddress((void**)&coq,  g_coq);
    cudaGetSymbolAddress((void**)&gxf,  g_gxf);
    cudaGetSymbolAddress((void**)&gxb,  g_gxb);
    cudaGetSymbolAddress((void**)&hh,   g_h);
    cudaGetSymbolAddress((void**)&lg,   g_lg);
    cudaGetSymbolAddress((void**)&wxqf, g_wxqf);
    cudaGetSymbolAddress((void**)&wxqb, g_wxqb);
    cudaGetSymbolAddress((void**)&cwq,  g_cwq);

    cudaFuncSetAttribute(lstm_cluster_kernel,
                         cudaFuncAttributeMaxDynamicSharedMemorySize, LS_TOTAL);

    {
        int ntot = 2 * ((C4T / 4) * G4) + 10 * (DN / 4) * C1;
        pack_all_kernel<<<(ntot + 255) / 256, 256>>>(
            wx_f, wx_b, w1, w2, w3, w4, wxqf, wxqb, cwq);
    }

    ln1_kernel<<<BT, 192>>>(hid_a, hid_b, ln1_g, ln1_b, xnq);
    conv_fp8_kernel<<<dim3(BT / 128, 8), 256>>>(xnq, cwq, b1, b2, b3, b4, cv);
    ln2_kernel<<<BT, 192>>>(cv, ln2_g, ln2_b, coq);
    gemm_fp8_dual_kernel<<<dim3(BT / 128, 16), 256>>>(
        coq, wxqf, wxqb, bf, bb, gxf, gxb);
    lstm_cluster_kernel<<<128, 256, LS_TOTAL>>>(gxf, gxb, wh_f, wh_b, amask, hh);
    gemm_tf32_kernel<<<dim3(BT / 128, 1), 256>>>(hh, wd, bd, lg, BT, LBL, 2 * HN);
    crf_kernel<<<BN, 32>>>(inputs, targets, trans, lg, (float*)d_out);
}

// round 16
// speedup vs baseline: 1.0982x; 1.0982x over previous
#include <cuda_runtime.h>
#include <math.h>
#include <stdint.h>

#define BN   64
#define TN   512
#define BT   32768
#define DN   1536
#define C1   192
#define C4T  768
#define HN   256
#define G4   1024
#define LBL  20

// ---------------- scratch (static device memory) ------------------------------
__device__ uint32_t g_xnq [ (size_t)BT * DN / 4 ];
__device__ float    g_cv  [ (size_t)BT * C4T    ];
__device__ uint32_t g_coq [ (size_t)BT * C4T / 4];
__device__ float    g_gxf [ (size_t)BT * G4     ];
__device__ float    g_gxb [ (size_t)BT * G4     ];
__device__ float    g_h   [ (size_t)BT * 2 * HN ];
__device__ float    g_lg  [ (size_t)BT * LBL    ];
__device__ uint32_t g_wxqf[ (C4T / 4) * G4 ];
__device__ uint32_t g_wxqb[ (C4T / 4) * G4 ];
__device__ uint32_t g_cwq [ 10 * (DN / 4) * C1 ];

// ---------------- helpers -----------------------------------------------------
__device__ __forceinline__ uint32_t packbf(float lo, float hi) {
    uint32_t u;
    asm("cvt.rn.bf16x2.f32 %0, %1, %2;" : "=r"(u) : "f"(hi), "f"(lo));
    return u;
}
__device__ __forceinline__ uint32_t pack4e4m3(float e0, float e1, float e2, float e3) {
    uint16_t lo, hi;
    asm("cvt.rn.satfinite.e4m3x2.f32 %0, %1, %2;" : "=h"(lo) : "f"(e1), "f"(e0));
    asm("cvt.rn.satfinite.e4m3x2.f32 %0, %1, %2;" : "=h"(hi) : "f"(e3), "f"(e2));
    return (uint32_t)lo | ((uint32_t)hi << 16);
}
__device__ __forceinline__ uint32_t f2tf32(float f) {
    uint32_t u;
    asm("cvt.rna.tf32.f32 %0, %1;" : "=r"(u) : "f"(f));
    return u;
}
__device__ __forceinline__ float ftanh(float x) {
    float y;
    asm("tanh.approx.f32 %0, %1;" : "=f"(y) : "f"(x));
    return y;
}
__device__ __forceinline__ float fsig(float x) {
    return 0.5f * ftanh(0.5f * x) + 0.5f;
}
__device__ __forceinline__ void mma_fp8(float* c, uint32_t a0, uint32_t a1,
                                        uint32_t a2, uint32_t a3,
                                        uint32_t b0, uint32_t b1) {
    asm volatile(
        "mma.sync.aligned.m16n8k32.row.col.f32.e4m3.e4m3.f32 "
        "{%0,%1,%2,%3}, {%4,%5,%6,%7}, {%8,%9}, {%0,%1,%2,%3};\n"
        : "+f"(c[0]), "+f"(c[1]), "+f"(c[2]), "+f"(c[3])
        : "r"(a0), "r"(a1), "r"(a2), "r"(a3), "r"(b0), "r"(b1));
}
__device__ __forceinline__ void mma_bf16(float* c, uint32_t a0, uint32_t a1,
                                         uint32_t a2, uint32_t a3,
                                         uint32_t b0, uint32_t b1) {
    asm volatile(
        "mma.sync.aligned.m16n8k16.row.col.f32.bf16.bf16.f32 "
        "{%0,%1,%2,%3}, {%4,%5,%6,%7}, {%8,%9}, {%0,%1,%2,%3};\n"
        : "+f"(c[0]), "+f"(c[1]), "+f"(c[2]), "+f"(c[3])
        : "r"(a0), "r"(a1), "r"(a2), "r"(a3), "r"(b0), "r"(b1));
}
__device__ __forceinline__ void mma_tf32(float* c, uint32_t a0, uint32_t a1,
                                         uint32_t a2, uint32_t a3,
                                         uint32_t b0, uint32_t b1) {
    asm volatile(
        "mma.sync.aligned.m16n8k8.row.col.f32.tf32.tf32.f32 "
        "{%0,%1,%2,%3}, {%4,%5,%6,%7}, {%8,%9}, {%0,%1,%2,%3};\n"
        : "+f"(c[0]), "+f"(c[1]), "+f"(c[2]), "+f"(c[3])
        : "r"(a0), "r"(a1), "r"(a2), "r"(a3), "r"(b0), "r"(b1));
}
__device__ __forceinline__ void ldsm4(uint32_t* a, uint32_t saddr) {
    asm volatile("ldmatrix.sync.aligned.m8n8.x4.shared.b16 {%0,%1,%2,%3}, [%4];"
                 : "=r"(a[0]), "=r"(a[1]), "=r"(a[2]), "=r"(a[3]) : "r"(saddr));
}
__device__ __forceinline__ uint32_t smem_u32(const void* p) {
    uint32_t a;
    asm("{ .reg .u64 t; cvta.to.shared.u64 t, %1; cvt.u32.u64 %0, t; }"
        : "=r"(a) : "l"(p));
    return a;
}
#define MB_INIT(a, c) asm volatile("mbarrier.init.shared.b64 [%0], %1;" :: "r"(a), "r"((uint32_t)(c)) : "memory")
#define MB_WAIT(a, par) do { \
    asm volatile("{\n\t.reg .pred P1;\n\tWL%=:\n\t" \
        "mbarrier.try_wait.parity.acquire.cta.shared::cta.b64 P1, [%0], %1, 0x989680;\n\t" \
        "@P1 bra WD%=;\n\tbra WL%=;\n\tWD%=:\n\t}" :: "r"(a), "r"((uint32_t)(par)) : "memory"); } while (0)
#define MB_ARRIVE_REMOTE(a) \
    asm volatile("mbarrier.arrive.shared::cluster.b64 _, [%0];" :: "r"(a) : "memory")

#define AST2 20
#define BSTX 136
#define BST3 200
#define AST 36
#define BST 68

// ---------------- merged fp8 weight prepack -------------------------------------
__global__ __launch_bounds__(256) void pack_all_kernel(
    const float* __restrict__ wx_f, const float* __restrict__ wx_b,
    const float* __restrict__ w1, const float* __restrict__ w2,
    const float* __restrict__ w3, const float* __restrict__ w4,
    uint32_t* __restrict__ wxqf, uint32_t* __restrict__ wxqb,
    uint32_t* __restrict__ cwq)
{
    int idx = blockIdx.x * 256 + threadIdx.x;
    const int SX = (C4T / 4) * G4;
    if (idx < SX) {
        int kq = idx >> 10, n = idx & 1023;
        const float* s = wx_f + (size_t)(4 * kq) * G4 + n;
        wxqf[idx] = pack4e4m3(s[0], s[G4], s[2 * G4], s[3 * G4]);
        return;
    }
    idx -= SX;
    if (idx < SX) {
        int kq = idx >> 10, n = idx & 1023;
        const float* s = wx_b + (size_t)(4 * kq) * G4 + n;
        wxqb[idx] = pack4e4m3(s[0], s[G4], s[2 * G4], s[3 * G4]);
        return;
    }
    idx -= SX;
    const int T1 = (DN / 4) * C1;
    const float* src;
    uint32_t* dst;
    if (idx < 1 * T1)      { src = w1; dst = cwq; }
    else if (idx < 3 * T1) { src = w2; dst = cwq + (size_t)1 * T1; idx -= 1 * T1; }
    else if (idx < 6 * T1) { src = w3; dst = cwq + (size_t)3 * T1; idx -= 3 * T1; }
    else if (idx < 10 * T1){ src = w4; dst = cwq + (size_t)6 * T1; idx -= 6 * T1; }
    else return;
    int kqg = idx / C1, n = idx - kqg * C1;
    const float* s = src + (size_t)(4 * kqg) * C1 + n;
    dst[idx] = pack4e4m3(s[0], s[C1], s[2 * C1], s[3 * C1]);
}

// ---------------- LayerNorm 1: single-pass, register-cached ---------------------
__global__ __launch_bounds__(192) void ln1_kernel(
    const float* __restrict__ ha, const float* __restrict__ hb,
    const float* __restrict__ g,  const float* __restrict__ be,
    uint32_t* __restrict__ out4)
{
    int row = blockIdx.x;
    int tid = threadIdx.x;
    int d0 = tid * 8;
    float4 v0, v1;
    if (tid < 96) {
        const float* A = ha + (size_t)row * 768 + d0;
        v0 = *reinterpret_cast<const float4*>(A);
        v1 = *reinterpret_cast<const float4*>(A + 4);
    } else {
        const float* B = hb + (size_t)row * 768 + (d0 - 768);
        v0 = *reinterpret_cast<const float4*>(B);
        v1 = *reinterpret_cast<const float4*>(B + 4);
    }
    float s  = v0.x + v0.y + v0.z + v0.w + v1.x + v1.y + v1.z + v1.w;
    float s2 = v0.x*v0.x + v0.y*v0.y + v0.z*v0.z + v0.w*v0.w
             + v1.x*v1.x + v1.y*v1.y + v1.z*v1.z + v1.w*v1.w;
#pragma unroll
    for (int o = 16; o; o >>= 1) {
        s  += __shfl_xor_sync(0xffffffffu, s, o);
        s2 += __shfl_xor_sync(0xffffffffu, s2, o);
    }
    __shared__ float ws[6], wq[6];
    int wid = tid >> 5;
    if ((tid & 31) == 0) { ws[wid] = s; wq[wid] = s2; }
    __syncthreads();
    float S = ws[0] + ws[1] + ws[2] + ws[3] + ws[4] + ws[5];
    float Q = wq[0] + wq[1] + wq[2] + wq[3] + wq[4] + wq[5];
    float mean = S * (1.f / DN);
    float var  = Q * (1.f / DN) - mean * mean;
    float rstd = rsqrtf(var + 1e-5f);
    float4 g0 = *reinterpret_cast<const float4*>(g + d0);
    float4 g1 = *reinterpret_cast<const float4*>(g + d0 + 4);
    float4 b0 = *reinterpret_cast<const float4*>(be + d0);
    float4 b1 = *reinterpret_cast<const float4*>(be + d0 + 4);
    uint32_t* O = out4 + (size_t)row * (DN / 4) + tid * 2;
    O[0] = pack4e4m3((v0.x - mean) * rstd * g0.x + b0.x,
                     (v0.y - mean) * rstd * g0.y + b0.y,
                     (v0.z - mean) * rstd * g0.z + b0.z,
                     (v0.w - mean) * rstd * g0.w + b0.w);
    O[1] = pack4e4m3((v1.x - mean) * rstd * g1.x + b1.x,
                     (v1.y - mean) * rstd * g1.y + b1.y,
                     (v1.z - mean) * rstd * g1.z + b1.z,
                     (v1.w - mean) * rstd * g1.w + b1.w);
}

// ---------------- LayerNorm 2: single-pass, register-cached ---------------------
__global__ __launch_bounds__(192) void ln2_kernel(
    const float* __restrict__ in, const float* __restrict__ g,
    const float* __restrict__ be, uint32_t* __restrict__ out4)
{
    int row = blockIdx.x;
    int tid = threadIdx.x;
    int d0 = tid * 4;
    float4 v = *reinterpret_cast<const float4*>(in + (size_t)row * C4T + d0);
    float s  = v.x + v.y + v.z + v.w;
    float s2 = v.x*v.x + v.y*v.y + v.z*v.z + v.w*v.w;
#pragma unroll
    for (int o = 16; o; o >>= 1) {
        s  += __shfl_xor_sync(0xffffffffu, s, o);
        s2 += __shfl_xor_sync(0xffffffffu, s2, o);
    }
    __shared__ float ws[6], wq[6];
    int wid = tid >> 5;
    if ((tid & 31) == 0) { ws[wid] = s; wq[wid] = s2; }
    __syncthreads();
    float S = ws[0] + ws[1] + ws[2] + ws[3] + ws[4] + ws[5];
    float Q = wq[0] + wq[1] + wq[2] + wq[3] + wq[4] + wq[5];
    float mean = S * (1.f / C4T);
    float var  = Q * (1.f / C4T) - mean * mean;
    float rstd = rsqrtf(var + 1e-5f);
    float4 gg = *reinterpret_cast<const float4*>(g + d0);
    float4 bb = *reinterpret_cast<const float4*>(be + d0);
    out4[(size_t)row * (C4T / 4) + tid] =
        pack4e4m3((v.x - mean) * rstd * gg.x + bb.x,
                  (v.y - mean) * rstd * gg.y + bb.y,
                  (v.z - mean) * rstd * gg.z + bb.z,
                  (v.w - mean) * rstd * gg.w + bb.w);
}

// ---------------- fp8 dual xWx GEMM (unchanged) ---------------------------------
__global__ __launch_bounds__(256) void gemm_fp8_dual_kernel(
    const uint32_t* __restrict__ A4,
    const uint32_t* __restrict__ Wqf, const uint32_t* __restrict__ Wqb,
    const float* __restrict__ biasf, const float* __restrict__ biasb,
    float* __restrict__ Cf, float* __restrict__ Cb)
{
    const int Nn = G4;
    __shared__ uint32_t As[2][128 * AST2];
    __shared__ uint32_t Bs[2][16 * BSTX];
    int tid = threadIdx.x;
    int half = blockIdx.y >> 3;
    int n0 = (blockIdx.y & 7) * 128;
    const uint32_t* Wq   = half ? Wqb : Wqf;
    const float*    bias = half ? biasb : biasf;
    float*          Cc   = half ? Cb : Cf;
    int m0 = blockIdx.x * 128;
    int wid = tid >> 5, lane = tid & 31;
    int wm0 = (wid & 3) * 32, wn0 = (wid >> 2) * 64;
    int g = lane >> 2, tg = lane & 3;
    const int K4 = C4T >> 2;

    float acc[2][8][4];
#pragma unroll
    for (int mt = 0; mt < 2; mt++)
#pragma unroll
        for (int nt = 0; nt < 8; nt++)
#pragma unroll
            for (int i = 0; i < 4; i++) acc[mt][nt][i] = 0.f;

    uint32_t abase[2];
#pragma unroll
    for (int sb = 0; sb < 2; sb++)
        abase[sb] = (uint32_t)__cvta_generic_to_shared(
            &As[sb][(wm0 + (lane & 15)) * AST2 + (lane >> 4) * 4]);

    uint4 pa[2], pb[2];
    const int nk = C4T / 64;
    auto loadA = [&](int kt) {
#pragma unroll
        for (int j = 0; j < 2; j++) {
            int idx4 = tid + j * 256;
            int row = idx4 >> 2, qc = (idx4 & 3) << 2;
            pa[j] = *reinterpret_cast<const uint4*>(A4 + (size_t)(m0 + row) * K4 + kt * 16 + qc);
        }
    };
    auto loadB = [&](int kt) {
#pragma unroll
        for (int j = 0; j < 2; j++) {
            int idx4 = tid + j * 256;
            int kp = idx4 >> 5, nc = (idx4 & 31) << 2;
            pb[j] = *reinterpret_cast<const uint4*>(Wq + (size_t)(kt * 16 + kp) * Nn + n0 + nc);
        }
    };
    auto stage = [&](int sb) {
#pragma unroll
        for (int j = 0; j < 2; j++) {
            int idx4 = tid + j * 256;
            int row = idx4 >> 2, qc = (idx4 & 3) << 2;
            *reinterpret_cast<uint4*>(&As[sb][row * AST2 + qc]) = pa[j];
        }
#pragma unroll
        for (int j = 0; j < 2; j++) {
            int idx4 = tid + j * 256;
            int kp = idx4 >> 5, nc = (idx4 & 31) << 2;
            *reinterpret_cast<uint4*>(&Bs[sb][kp * BSTX + nc]) = pb[j];
        }
    };

    loadA(0); loadB(0);
    stage(0);
    __syncthreads();
    for (int kt = 0; kt < nk; kt++) {
        int cur = kt & 1;
        if (kt + 1 < nk) { loadA(kt + 1); loadB(kt + 1); }
        const uint32_t* Bc = Bs[cur];
        uint32_t ab = abase[cur];
#pragma unroll
        for (int ks = 0; ks < 2; ks++) {
            int kk4 = ks * 8;
            uint32_t a[2][4], b[8][2];
#pragma unroll
            for (int mt = 0; mt < 2; mt++)
                ldsm4(a[mt], ab + (uint32_t)((mt * 16 * AST2 + kk4) * 4));
#pragma unroll
            for (int nt = 0; nt < 8; nt++) {
                int col = wn0 + nt * 8 + g;
                b[nt][0] = Bc[(kk4 + tg    ) * BSTX + col];
                b[nt][1] = Bc[(kk4 + tg + 4) * BSTX + col];
            }
#pragma unroll
            for (int mt = 0; mt < 2; mt++)
#pragma unroll
                for (int nt = 0; nt < 8; nt++)
                    mma_fp8(acc[mt][nt], a[mt][0], a[mt][1], a[mt][2], a[mt][3],
                            b[nt][0], b[nt][1]);
        }
        if (kt + 1 < nk) {
            stage(cur ^ 1);
            __syncthreads();
        }
    }
#pragma unroll
    for (int mt = 0; mt < 2; mt++)
#pragma unroll
        for (int nt = 0; nt < 8; nt++) {
            int col = n0 + wn0 + nt * 8 + 2 * tg;
#pragma unroll
            for (int i = 0; i < 4; i++) {
                int row = m0 + wm0 + mt * 16 + g + (i >> 1) * 8;
                int c = col + (i & 1);
                Cc[(size_t)row * Nn + c] = acc[mt][nt][i] + bias[c];
            }
        }
}

// ---------------- Conv fp8: 128x192 tile (R13 proven), heavy-first order --------
// grid (BT/128, 4): conv = 3 - blockIdx.y (heavy blocks launch first).
__global__ __launch_bounds__(256) void conv_fp8_kernel(
    const uint32_t* __restrict__ xnq, const uint32_t* __restrict__ cwq,
    const float* __restrict__ cb1, const float* __restrict__ cb2,
    const float* __restrict__ cb3, const float* __restrict__ cb4,
    float* __restrict__ cv)
{
    __shared__ uint32_t As[2][128 * AST2];
    __shared__ uint32_t Bs[2][16 * BST3];
    int tid = threadIdx.x;
    int m0 = blockIdx.x * 128;
    int conv = 3 - blockIdx.y;
    int bidx = m0 >> 9;
    int t0   = m0 & 511;
    int tap0 = (conv == 0) ? 0 : (conv == 1) ? 1 : (conv == 2) ? 3 : 6;
    const float* bias = (conv == 0) ? cb1 : (conv == 1) ? cb2 : (conv == 2) ? cb3 : cb4;
    int ntaps = conv + 1;
    int dmin  = (conv < 2) ? 1 : 0;

    int wid = tid >> 5, lane = tid & 31;
    int wm0 = (wid & 3) * 32, wn0 = (wid >> 2) * 96;
    int g = lane >> 2, tg = lane & 3;

    float acc[2][12][4];
#pragma unroll
    for (int mt = 0; mt < 2; mt++)
#pragma unroll
        for (int nt = 0; nt < 12; nt++)
#pragma unroll
            for (int i = 0; i < 4; i++) acc[mt][nt][i] = 0.f;

    uint32_t abase[2];
#pragma unroll
    for (int sb = 0; sb < 2; sb++)
        abase[sb] = (uint32_t)__cvta_generic_to_shared(
            &As[sb][(wm0 + (lane & 15)) * AST2 + (lane >> 4) * 4]);

    const int nkt = DN / 64;
    int total = ntaps * nkt;
    const int K4 = DN / 4;

    uint4 pa[2], pb[3];
    auto loadA = [&](int it) {
        int ti = it / nkt, kt = it - ti * nkt;
        int shift = dmin + ti - 1;
#pragma unroll
        for (int j = 0; j < 2; j++) {
            int idx4 = tid + j * 256;
            int row = idx4 >> 2, qc = (idx4 & 3) << 2;
            int tsrc = t0 + row + shift;
            if (tsrc >= 0 && tsrc < TN)
                pa[j] = *reinterpret_cast<const uint4*>(
                    xnq + (size_t)((bidx << 9) + tsrc) * K4 + kt * 16 + qc);
            else
                pa[j] = make_uint4(0u, 0u, 0u, 0u);
        }
    };
    auto loadB = [&](int it) {
        int ti = it / nkt, kt = it - ti * nkt;
#pragma unroll
        for (int j = 0; j < 3; j++) {
            int idx4 = tid + j * 256;
            int kp = idx4 / 48, nc = (idx4 % 48) << 2;
            pb[j] = *reinterpret_cast<const uint4*>(
                cwq + ((size_t)(tap0 + ti) * (DN / 4) + kt * 16 + kp) * C1 + nc);
        }
    };
    auto stage = [&](int sb) {
#pragma unroll
        for (int j = 0; j < 2; j++) {
            int idx4 = tid + j * 256;
            int row = idx4 >> 2, qc = (idx4 & 3) << 2;
            *reinterpret_cast<uint4*>(&As[sb][row * AST2 + qc]) = pa[j];
        }
#pragma unroll
        for (int j = 0; j < 3; j++) {
            int idx4 = tid + j * 256;
            int kp = idx4 / 48, nc = (idx4 % 48) << 2;
            *reinterpret_cast<uint4*>(&Bs[sb][kp * BST3 + nc]) = pb[j];
        }
    };

    loadA(0); loadB(0);
    stage(0);
    __syncthreads();
    for (int it = 0; it < total; it++) {
        int cur = it & 1;
        if (it + 1 < total) { loadA(it + 1); loadB(it + 1); }
        const uint32_t* Bc = Bs[cur];
        uint32_t ab = abase[cur];
#pragma unroll
        for (int ks = 0; ks < 2; ks++) {
            int kk4 = ks * 8;
            uint32_t a[2][4], b[12][2];
#pragma unroll
            for (int mt = 0; mt < 2; mt++)
                ldsm4(a[mt], ab + (uint32_t)((mt * 16 * AST2 + kk4) * 4));
#pragma unroll
            for (int nt = 0; nt < 12; nt++) {
                int col = wn0 + nt * 8 + g;
                b[nt][0] = Bc[(kk4 + tg    ) * BST3 + col];
                b[nt][1] = Bc[(kk4 + tg + 4) * BST3 + col];
            }
#pragma unroll
            for (int mt = 0; mt < 2; mt++)
#pragma unroll
                for (int nt = 0; nt < 12; nt++)
                    mma_fp8(acc[mt][nt], a[mt][0], a[mt][1], a[mt][2], a[mt][3],
                            b[nt][0], b[nt][1]);
        }
        if (it + 1 < total) {
            stage(cur ^ 1);
            __syncthreads();
        }
    }
#pragma unroll
    for (int mt = 0; mt < 2; mt++)
#pragma unroll
        for (int nt = 0; nt < 12; nt++) {
            int cl = wn0 + nt * 8 + 2 * tg;
#pragma unroll
            for (int i = 0; i < 4; i++) {
                int row = m0 + wm0 + mt * 16 + g + (i >> 1) * 8;
                int c   = cl + (i & 1);
                float v = acc[mt][nt][i] + bias[c];
                cv[(size_t)row * C4T + conv * C1 + c] = fmaxf(v, 0.f);
            }
        }
}

// ---------------- TF32 GEMM (logits) --------------------------------------------
__global__ __launch_bounds__(256) void gemm_tf32_kernel(
    const float* __restrict__ A, const float* __restrict__ W,
    const float* __restrict__ bias, float* __restrict__ Cc,
    int M, int Nn, int Kk)
{
    __shared__ uint32_t As[128 * AST];
    __shared__ uint32_t Bs[32 * BST];
    int tid = threadIdx.x;
    int m0 = blockIdx.x * 128, n0 = blockIdx.y * 64;
    int wid = tid >> 5, lane = tid & 31;
    int wm0 = (wid & 3) * 32, wn0 = (wid >> 2) * 32;
    int g = lane >> 2, tg = lane & 3;
    float acc[2][4][4];
#pragma unroll
    for (int mt = 0; mt < 2; mt++)
#pragma unroll
        for (int nt = 0; nt < 4; nt++)
#pragma unroll
            for (int i = 0; i < 4; i++) acc[mt][nt][i] = 0.f;
    float4 pa[4], pb[2];
    int nk = Kk / 32;
    auto loadA = [&](int kt) {
#pragma unroll
        for (int j = 0; j < 4; j++) {
            int idx4 = tid + j * 256;
            int row = idx4 >> 3, kc = (idx4 & 7) << 2;
            pa[j] = *reinterpret_cast<const float4*>(A + (size_t)(m0 + row) * Kk + kt * 32 + kc);
        }
    };
    auto loadB = [&](int kt) {
#pragma unroll
        for (int j = 0; j < 2; j++) {
            int idx4 = tid + j * 256;
            int row = idx4 >> 4, nc = (idx4 & 15) << 2;
            int ncol = n0 + nc;
            const float* Wr = W + (size_t)(kt * 32 + row) * Nn;
            float4 v;
            if (ncol + 3 < Nn) v = *reinterpret_cast<const float4*>(Wr + ncol);
            else {
                v.x = (ncol + 0 < Nn) ? Wr[ncol + 0] : 0.f;
                v.y = (ncol + 1 < Nn) ? Wr[ncol + 1] : 0.f;
                v.z = (ncol + 2 < Nn) ? Wr[ncol + 2] : 0.f;
                v.w = (ncol + 3 < Nn) ? Wr[ncol + 3] : 0.f;
            }
            pb[j] = v;
        }
    };
    auto stage = [&]() {
#pragma unroll
        for (int j = 0; j < 4; j++) {
            int idx4 = tid + j * 256;
            int row = idx4 >> 3, kc = (idx4 & 7) << 2;
            As[row * AST + kc + 0] = f2tf32(pa[j].x);
            As[row * AST + kc + 1] = f2tf32(pa[j].y);
            As[row * AST + kc + 2] = f2tf32(pa[j].z);
            As[row * AST + kc + 3] = f2tf32(pa[j].w);
        }
#pragma unroll
        for (int j = 0; j < 2; j++) {
            int idx4 = tid + j * 256;
            int row = idx4 >> 4, nc = (idx4 & 15) << 2;
            Bs[row * BST + nc + 0] = f2tf32(pb[j].x);
            Bs[row * BST + nc + 1] = f2tf32(pb[j].y);
            Bs[row * BST + nc + 2] = f2tf32(pb[j].z);
            Bs[row * BST + nc + 3] = f2tf32(pb[j].w);
        }
    };
    loadA(0); loadB(0);
    for (int kt = 0; kt < nk; kt++) {
        __syncthreads();
        stage();
        __syncthreads();
        if (kt + 1 < nk) { loadA(kt + 1); loadB(kt + 1); }
#pragma unroll
        for (int ks = 0; ks < 4; ks++) {
            int kk = ks * 8;
            uint32_t a[2][4], b[4][2];
#pragma unroll
            for (int mt = 0; mt < 2; mt++) {
                int r0 = wm0 + mt * 16 + g;
                a[mt][0] = As[(r0    ) * AST + kk + tg];
                a[mt][1] = As[(r0 + 8) * AST + kk + tg];
                a[mt][2] = As[(r0    ) * AST + kk + tg + 4];
                a[mt][3] = As[(r0 + 8) * AST + kk + tg + 4];
            }
#pragma unroll
            for (int nt = 0; nt < 4; nt++) {
                int col = wn0 + nt * 8 + g;
                b[nt][0] = Bs[(kk + tg    ) * BST + col];
                b[nt][1] = Bs[(kk + tg + 4) * BST + col];
            }
#pragma unroll
            for (int mt = 0; mt < 2; mt++)
#pragma unroll
                for (int nt = 0; nt < 4; nt++)
                    mma_tf32(acc[mt][nt], a[mt][0], a[mt][1], a[mt][2], a[mt][3],
                             b[nt][0], b[nt][1]);
        }
    }
#pragma unroll
    for (int mt = 0; mt < 2; mt++)
#pragma unroll
        for (int nt = 0; nt < 4; nt++) {
            int col = n0 + wn0 + nt * 8 + 2 * tg;
#pragma unroll
            for (int i = 0; i < 4; i++) {
                int row = m0 + wm0 + mt * 16 + g + (i >> 1) * 8;
                int c = col + (i & 1);
                if (c < Nn) Cc[(size_t)row * Nn + c] = acc[mt][nt][i] + bias[c];
            }
        }
}

// ---------------- LSTM: 4-CTA cluster, mbarrier handoff (unchanged R13) ---------
#define LSW   (256 * 132 * 4)
#define LSH2  (2 * 128 * 8 * 4)
#define LSZ   (256 * 5 * 4)
#define LSMB  (LSW + LSH2 + LSZ)
#define LS_TOTAL (LSMB + 16)

__global__ void __cluster_dims__(4, 1, 1) __launch_bounds__(256)
lstm_cluster_kernel(
    const float* __restrict__ gxf, const float* __restrict__ gxb,
    const float* __restrict__ wh_f, const float* __restrict__ wh_b,
    const int* __restrict__ amask, float* __restrict__ hout)
{
    extern __shared__ char sm_[];
    uint32_t* whs2 = (uint32_t*)sm_;
    uint32_t* h2   = (uint32_t*)(sm_ + LSW);
    float*    zbuf = (float*)(sm_ + LSW + LSH2);
    uint32_t  mb   = smem_u32(sm_ + LSMB);

    int tid = threadIdx.x;
    uint32_t rank;
    asm("mov.u32 %0, %%cluster_ctarank;" : "=r"(rank));
    int grp = blockIdx.x >> 2;
    int dir = grp >> 4;
    int b0  = (grp & 15) * 4;
    const float* __restrict__ Wh = dir ? wh_b : wh_f;
    const float* __restrict__ gx = dir ? gxb : gxf;

    for (int i = tid; i < 256 * 128; i += 256) {
        int lcol = i >> 7, kp = i & 127;
        int gcol = ((lcol >> 6) << 8) + (int)rank * 64 + (lcol & 63);
        whs2[lcol * 132 + kp] = packbf(Wh[(2 * kp) * G4 + gcol],
                                       Wh[(2 * kp + 1) * G4 + gcol]);
    }
    for (int i = tid; i < 2048; i += 256) h2[i] = 0u;
    if (tid == 0) { MB_INIT(mb, 4); MB_INIT(mb + 8, 4); }

    int lane = tid & 31, wrp = tid >> 5;
    int g = lane >> 2, tg = lane & 3;
    int pb = tid >> 6, pj = tid & 63;
    int bb = b0 + pb;
    float h_r = 0.f, c_r = 0.f, op_r = 0.f;

    uint32_t ha[2][4];
    {
        int k = (int)rank * 64 + pj;
        uint32_t loc;
        const void* p = (const void*)((const char*)h2 + ((k >> 1) * 8 + pb) * 4 + (k & 1) * 2);
        asm("{ .reg .u64 t; cvta.to.shared.u64 t, %1; cvt.u32.u64 %0, t; }"
            : "=r"(loc) : "l"(p));
#pragma unroll
        for (int bf = 0; bf < 2; bf++) {
            uint32_t off = loc + bf * 4096;
#pragma unroll
            for (int r = 0; r < 4; r++)
                asm("mapa.shared::cluster.u32 %0, %1, %2;"
                    : "=r"(ha[bf][r]) : "r"(off), "r"(r));
        }
    }
    uint32_t mba[2][4];
#pragma unroll
    for (int bf = 0; bf < 2; bf++)
#pragma unroll
        for (int r = 0; r < 4; r++)
            asm("mapa.shared::cluster.u32 %0, %1, %2;"
                : "=r"(mba[bf][r]) : "r"(mb + bf * 8), "r"(r));

    asm volatile("barrier.cluster.arrive.aligned;" ::: "memory");
    asm volatile("barrier.cluster.wait.aligned;"   ::: "memory");

    int buf = 0, ph0 = 0, ph1 = 0;
    for (int s = 0; s < TN; s++) {
        int t = dir ? (TN - 1 - s) : s;
        size_t gb = ((size_t)(bb * TN + t)) * G4 + (size_t)rank * 64 + pj;
        float gx0 = gx[gb], gx1 = gx[gb + 256], gx2 = gx[gb + 512], gx3 = gx[gb + 768];
        int mv = amask[bb * TN + t];

        if (s > 0) {
            if (buf == 0) { MB_WAIT(mb, ph0);     ph0 ^= 1; }
            else          { MB_WAIT(mb + 8, ph1); ph1 ^= 1; }
        }

        const uint32_t* h2c = h2 + buf * 1024;
        float d0[4] = {0,0,0,0}, d1[4] = {0,0,0,0};
        float e0[4] = {0,0,0,0}, e1[4] = {0,0,0,0};
        int r0 = wrp * 32 + g;
#pragma unroll
        for (int kt = 0; kt < 8; kt++) {
            int kA = kt * 8, kB = (kt + 8) * 8;
            uint32_t bqA0 = h2c[(kA + tg) * 8 + g];
            uint32_t bqA1 = h2c[(kA + tg + 4) * 8 + g];
            uint32_t bqB0 = h2c[(kB + tg) * 8 + g];
            uint32_t bqB1 = h2c[(kB + tg + 4) * 8 + g];
            uint32_t a0, a1, a2, a3;
            a0 = whs2[(r0     ) * 132 + kA + tg];
            a1 = whs2[(r0 +  8) * 132 + kA + tg];
            a2 = whs2[(r0     ) * 132 + kA + tg + 4];
            a3 = whs2[(r0 +  8) * 132 + kA + tg + 4];
            mma_bf16(d0, a0, a1, a2, a3, bqA0, bqA1);
            a0 = whs2[(r0 + 16) * 132 + kA + tg];
            a1 = whs2[(r0 + 24) * 132 + kA + tg];
            a2 = whs2[(r0 + 16) * 132 + kA + tg + 4];
            a3 = whs2[(r0 + 24) * 132 + kA + tg + 4];
            mma_bf16(d1, a0, a1, a2, a3, bqA0, bqA1);
            a0 = whs2[(r0     ) * 132 + kB + tg];
            a1 = whs2[(r0 +  8) * 132 + kB + tg];
            a2 = whs2[(r0     ) * 132 + kB + tg + 4];
            a3 = whs2[(r0 +  8) * 132 + kB + tg + 4];
            mma_bf16(e0, a0, a1, a2, a3, bqB0, bqB1);
            a0 = whs2[(r0 + 16) * 132 + kB + tg];
            a1 = whs2[(r0 + 24) * 132 + kB + tg];
            a2 = whs2[(r0 + 16) * 132 + kB + tg + 4];
            a3 = whs2[(r0 + 24) * 132 + kB + tg + 4];
            mma_bf16(e1, a0, a1, a2, a3, bqB0, bqB1);
        }
        if (tg < 2) {
#pragma unroll
            for (int i = 0; i < 4; i++) {
                int col = 2 * tg + (i & 1);
                zbuf[(r0 + (i >> 1) * 8     ) * 5 + col] = d0[i] + e0[i];
                zbuf[(r0 + (i >> 1) * 8 + 16) * 5 + col] = d1[i] + e1[i];
            }
        }
        __syncthreads();

        int nb = buf ^ 1;
        {
            float zi = zbuf[(      pj) * 5 + pb] + gx0;
            float zf = zbuf[( 64 + pj) * 5 + pb] + gx1;
            float zg = zbuf[(128 + pj) * 5 + pb] + gx2;
            float zo = zbuf[(192 + pj) * 5 + pb] + gx3;
            float ii = fsig(zi);
            float ff = fsig(zf);
            float gg = ftanh(zg);
            float oo = fsig(zo);
            float cn = ff * c_r + ii * gg;
            float hn = oo * ftanh(cn);
            bool m = mv != 0;
            float hq = m ? hn : h_r;
            c_r  = m ? cn : c_r;
            op_r = m ? hn : op_r;
            h_r  = hq;
            hout[((size_t)(bb * TN + t)) * (2 * HN) + dir * HN + (int)rank * 64 + pj] = op_r;
            uint16_t hb16;
            asm("cvt.rn.bf16.f32 %0, %1;" : "=h"(hb16) : "f"(hq));
#pragma unroll
            for (int r = 0; r < 4; r++)
                asm volatile("st.shared::cluster.b16 [%0], %1;"
                             :: "r"(ha[nb][r]), "h"(hb16) : "memory");
        }
        __syncthreads();
        if (tid == 0) {
            asm volatile("fence.acq_rel.cluster;" ::: "memory");
#pragma unroll
            for (int r = 0; r < 4; r++)
                MB_ARRIVE_REMOTE(mba[nb][r]);
        }
        buf = nb;
    }
    asm volatile("barrier.cluster.arrive.aligned;" ::: "memory");
    asm volatile("barrier.cluster.wait.aligned;"   ::: "memory");
}

// ---------------- CRF: prefetched emits + fast math ------------------------------
__global__ __launch_bounds__(32) void crf_kernel(
    const int* __restrict__ inputs, const int* __restrict__ targets,
    const float* __restrict__ trans, const float* __restrict__ logits,
    float* __restrict__ out)
{
    int b = blockIdx.x;
    int lane = threadIdx.x;
    __shared__ float tr[LBL * LBL];
    __shared__ float alpha[LBL];
    for (int i = lane; i < LBL * LBL; i += 32) tr[i] = trans[i];
    int cnt = 0;
    for (int t = lane; t < TN; t += 32) cnt += (inputs[b * TN + t] != 0);
#pragma unroll
    for (int o = 16; o; o >>= 1) cnt += __shfl_xor_sync(0xffffffffu, cnt, o);
    int seqlen = cnt;
    const float* lg = logits + (size_t)b * TN * LBL;
    const int*   tg = targets + b * TN;
    float us = 0.f, bs = 0.f;
    for (int t = lane; t < TN; t += 32) {
        if (t < seqlen) us += lg[t * LBL + tg[t]];
        if (t >= 1 && t < seqlen) bs += tr[tg[t - 1] * LBL + tg[t]];
    }
#pragma unroll
    for (int o = 16; o; o >>= 1) {
        us += __shfl_xor_sync(0xffffffffu, us, o);
        bs += __shfl_xor_sync(0xffffffffu, bs, o);
    }
    __syncwarp();
    if (lane < LBL) alpha[lane] = lg[lane];
    __syncwarp();

    float emit = (lane < LBL) ? lg[LBL + lane] : 0.f;
    for (int t = 1; t < TN; t++) {
        float emitN = (lane < LBL && t + 1 < TN) ? lg[(t + 1) * LBL + lane] : 0.f;
        float newv = 0.f;
        if (lane < LBL) {
            float m = -1e30f;
#pragma unroll
            for (int i = 0; i < LBL; i++) m = fmaxf(m, alpha[i] + tr[i * LBL + lane]);
            float ss = 0.f;
#pragma unroll
            for (int i = 0; i < LBL; i++) ss += __expf(alpha[i] + tr[i * LBL + lane] - m);
            newv = m + __logf(ss) + emit;
        }
        __syncwarp();
        if (lane < LBL && t < seqlen) alpha[lane] = newv;
        __syncwarp();
        emit = emitN;
    }
    float a = (lane < LBL) ? alpha[lane] : -1e30f;
    float mx = a;
#pragma unroll
    for (int o = 16; o; o >>= 1) mx = fmaxf(mx, __shfl_xor_sync(0xffffffffu, mx, o));
    float e = (lane < LBL) ? __expf(a - mx) : 0.f;
#pragma unroll
    for (int o = 16; o; o >>= 1) e += __shfl_xor_sync(0xffffffffu, e, o);
    float lognorm = mx + __logf(e);
    if (lane == 0) out[b] = us + bs - lognorm;
}

// ---------------- launch -----------------------------------------------------------
extern "C" void kernel_launch(void* const* d_in, const int* in_sizes, int n_in,
                              void* d_out, int out_size)
{
    const int*   inputs = (const int*)  d_in[0];
    const int*   amask  = (const int*)  d_in[1];
    const int*   targets= (const int*)  d_in[2];
    const float* hid_a  = (const float*)d_in[3];
    const float* hid_b  = (const float*)d_in[4];
    const float* ln1_g  = (const float*)d_in[5];
    const float* ln1_b  = (const float*)d_in[6];
    const float* w1 = (const float*)d_in[7];
    const float* b1 = (const float*)d_in[8];
    const float* w2 = (const float*)d_in[9];
    const float* b2 = (const float*)d_in[10];
    const float* w3 = (const float*)d_in[11];
    const float* b3 = (const float*)d_in[12];
    const float* w4 = (const float*)d_in[13];
    const float* b4 = (const float*)d_in[14];
    const float* ln2_g = (const float*)d_in[15];
    const float* ln2_b = (const float*)d_in[16];
    const float* wx_f  = (const float*)d_in[17];
    const float* wh_f  = (const float*)d_in[18];
    const float* bf    = (const float*)d_in[19];
    const float* wx_b  = (const float*)d_in[20];
    const float* wh_b  = (const float*)d_in[21];
    const float* bb    = (const float*)d_in[22];
    const float* wd    = (const float*)d_in[23];
    const float* bd    = (const float*)d_in[24];
    const float* trans = (const float*)d_in[25];

    uint32_t *xnq, *coq, *wxqf, *wxqb, *cwq;
    float *cv, *gxf, *gxb, *hh, *lg;
    cudaGetSymbolAddress((void**)&xnq,  g_xnq);
    cudaGetSymbolAddress((void**)&cv,   g_cv);
    cudaGetSymbolAddress((void**)&coq,  g_coq);
    cudaGetSymbolAddress((void**)&gxf,  g_gxf);
    cudaGetSymbolAddress((void**)&gxb,  g_gxb);
    cudaGetSymbolAddress((void**)&hh,   g_h);
    cudaGetSymbolAddress((void**)&lg,   g_lg);
    cudaGetSymbolAddress((void**)&wxqf, g_wxqf);
    cudaGetSymbolAddress((void**)&wxqb, g_wxqb);
    cudaGetSymbolAddress((void**)&cwq,  g_cwq);

    cudaFuncSetAttribute(lstm_cluster_kernel,
                         cudaFuncAttributeMaxDynamicSharedMemorySize, LS_TOTAL);

    {
        int ntot = 2 * ((C4T / 4) * G4) + 10 * (DN / 4) * C1;
        pack_all_kernel<<<(ntot + 255) / 256, 256>>>(
            wx_f, wx_b, w1, w2, w3, w4, wxqf, wxqb, cwq);
    }

    ln1_kernel<<<BT, 192>>>(hid_a, hid_b, ln1_g, ln1_b, xnq);
    conv_fp8_kernel<<<dim3(BT / 128, 4), 256>>>(xnq, cwq, b1, b2, b3, b4, cv);
    ln2_kernel<<<BT, 192>>>(cv, ln2_g, ln2_b, coq);
    gemm_fp8_dual_kernel<<<dim3(BT / 128, 16), 256>>>(
        coq, wxqf, wxqb, bf, bb, gxf, gxb);
    lstm_cluster_kernel<<<128, 256, LS_TOTAL>>>(gxf, gxb, wh_f, wh_b, amask, hh);
    gemm_tf32_kernel<<<dim3(BT / 128, 1), 256>>>(hh, wd, bd, lg, BT, LBL, 2 * HN);
    crf_kernel<<<BN, 32>>>(inputs, targets, trans, lg, (float*)d_out);
}